// round 16
// baseline (speedup 1.0000x reference)
#include <cuda_runtime.h>
#include <cuda_fp16.h>
#include <math.h>
#include <stdint.h>

#define BB  512
#define TT  55
#define CC  512
#define DD  512
#define KK  64
#define LL  3
#define OO  512
#define BT  (BB*TT)      // 28160
#define BD  (BB*DD)      // 262144
#define G4  2048

// ---------------- device scratch ----------------
__device__ float g_gx[(size_t)LL*BT*G4];
__device__ float g_Grx[(size_t)LL*BT*KK];
__device__ float g_d0all[(size_t)BT*KK];
__device__ float g_dd0[(size_t)BT*DD];
__device__ float g_h[4*LL*BD];                    // fp32 h ring (k1 reads)
__device__ __half g_hbh[4*LL*BD];                 // fp16 hi ring
__device__ __half g_hbl[4*LL*BD];                 // fp16 lo ring
__device__ float g_c[LL*BD];
__device__ float g_d[LL*BB*KK];
__device__ float g_dd[2*BD];
__device__ float g_part[6*(size_t)BB*G4];
__device__ float g_ppart[3*(size_t)BB*OO];
__device__ __half g_xbh[(size_t)BT*CC];           // X fp16 hi
__device__ __half g_xbl[(size_t)BT*CC];
// pre-transposed fp16 weight images, [n][k=512] row-major (12 images, hi only)
#define WIMG_TOT 10223616
__device__ __half g_wih[WIMG_TOT];

__device__ __forceinline__ float sigm(float x) { return 1.0f/(1.0f+expf(-x)); }

// ---- mma.sync m16n8k16 fp16 inputs, fp32 accum (base-target PTX) ----
__device__ __forceinline__ void mma16816(float* d, const uint32_t* a, const uint32_t* b) {
    asm volatile("mma.sync.aligned.m16n8k16.row.col.f32.f16.f16.f32 "
        "{%0,%1,%2,%3}, {%4,%5,%6,%7}, {%8,%9}, {%0,%1,%2,%3};"
        : "+f"(d[0]), "+f"(d[1]), "+f"(d[2]), "+f"(d[3])
        : "r"(a[0]), "r"(a[1]), "r"(a[2]), "r"(a[3]), "r"(b[0]), "r"(b[1]));
}
__device__ __forceinline__ void ldsm_x4(uint32_t* r, uint32_t addr) {
    asm volatile("ldmatrix.sync.aligned.m8n8.x4.shared.b16 {%0,%1,%2,%3}, [%4];"
        : "=r"(r[0]), "=r"(r[1]), "=r"(r[2]), "=r"(r[3]) : "r"(addr));
}
__device__ __forceinline__ uint32_t smem_u32(const void* p) {
    uint32_t a;
    asm("{ .reg .u64 t; cvta.to.shared.u64 t, %1; cvt.u32.u64 %0, t; }" : "=r"(a) : "l"(p));
    return a;
}
__device__ __forceinline__ void cp16(uint32_t dst, const void* src) {
    asm volatile("cp.async.cg.shared.global [%0], [%1], 16;" :: "r"(dst), "l"(src));
}
__device__ __forceinline__ void cp_commit() {
    asm volatile("cp.async.commit_group;" ::: "memory");
}
template<int N> __device__ __forceinline__ void cp_wait() {
    asm volatile("cp.async.wait_group %0;" :: "n"(N) : "memory");
}

// ---------------- key-gate body (256 threads; 8 batches per block) ----------------
struct K1A {
    const float *hp, *hn, *grx, *wr, *wl0, *wl1, *wd;
    float *dst, *dd;
    int l, t;
};
__device__ void k1_body(const K1A& a, int bx)
{
    __shared__ float dn_s[8][KK];
    const int tid = threadIdx.x;        // 256
    const int r   = tid >> 5;           // 0..7
    const int q   = tid & 31;
    const int b   = bx*8 + r;

    const long long gro = ((long long)b*TT + a.t)*KK;
    float acc0 = a.grx[gro + q];
    float acc1 = a.grx[gro + q + 32];
    for (int j = 0; j < a.l; j++) {
        const float* hnj = a.hn + (size_t)j*BD + (size_t)b*DD;
        const float* hpj = a.hp + (size_t)j*BD + (size_t)b*DD;
        const float* wrp = a.wr + (size_t)(CC + j*DD)*KK;
        const float* wlp = (j == 0 ? a.wl0 : a.wl1);
        float u0 = 0.f, u1 = 0.f;
#pragma unroll 4
        for (int m = 0; m < DD; m++) {
            float hv = hnj[m], pv = hpj[m];
            acc0 = fmaf(hv, wrp[(size_t)m*KK + q],      acc0);
            acc1 = fmaf(hv, wrp[(size_t)m*KK + q + 32], acc1);
            u0   = fmaf(pv, wlp[(size_t)m*KK + q],      u0);
            u1   = fmaf(pv, wlp[(size_t)m*KK + q + 32], u1);
        }
        acc0 += u0 * (1.0f/3.0f);
        acc1 += u1 * (1.0f/3.0f);
    }
    float dn0 = sigm(acc0) * a.dst[b*KK + q];
    float dn1 = sigm(acc1) * a.dst[b*KK + q + 32];
    a.dst[b*KK + q]      = dn0;
    a.dst[b*KK + q + 32] = dn1;
    dn_s[r][q]      = dn0;
    dn_s[r][q + 32] = dn1;
    __syncthreads();

    for (int e = tid; e < 8*DD; e += 256) {
        int r2 = e >> 9;
        int n  = e & 511;
        int bb = bx*8 + r2;
        float s = 0.0f;
#pragma unroll
        for (int qq = 0; qq < KK; qq++)
            s = fmaf(dn_s[r2][qq], a.wd[(size_t)qq*DD + n], s);
        a.dd[(size_t)bb*DD + n] = tanhf(s);
    }
}

// ---------------- mma stage kernel: fp16 2-term, 64x128 tile, 3 blocks/SM ----------------
// Tile M=64,N=128,K=512 (16 chunks of 32, double-buffered). A row-major fp16 hi/lo;
// B from pre-transposed [n][512] fp16 images. 8 warps (2x4), warp tile 32x32.
struct TPlane {
    const __half *Ah, *Al;          // [M][512]
    const __half *Bh;               // image base [Np][512]
    float* out; long long ldc;
    int xmax; int kind;             // 0 gemm, -1 idle, 1 -> k1[0], 2 -> k1[1]
};
struct TStage { TPlane p[11]; K1A k1[2]; };

#define SPB    80       // smem row pitch in BYTES (40 halves)
#define A_TILE 5120     // 64 rows x 80B
#define B_TILE 10240    // 128 rows x 80B
#define STGB   20480    // Ah + Al + Bh per buffer
#define NKC    16

__global__ void __launch_bounds__(256, 3)
mma_stage(TStage SA)
{
    extern __shared__ __align__(16) char sm[];

    const TPlane pl = SA.p[blockIdx.z];
    if (pl.kind < 0) return;
    if (pl.kind > 0) {
        int bx = blockIdx.y * gridDim.x + blockIdx.x;
        if (bx < 64) k1_body(SA.k1[pl.kind - 1], bx);
        return;
    }
    if ((int)blockIdx.x >= pl.xmax) return;

    const int tid = threadIdx.x;
    const int wid = tid >> 5, lid = tid & 31;
    const int wm = wid >> 2, wn = wid & 3;         // warp grid 2x4, warp tile 32x32
    const int gid = lid >> 2, tig = lid & 3;
    const int row0 = blockIdx.y * 64;
    const int col0 = blockIdx.x * 128;
    const uint32_t smb = smem_u32(sm);

    const int cr  = tid >> 2, csg = tid & 3;       // A rows 0..63, 16B seg
    const int br1 = (tid + 256) >> 2;              // B rows second half

    float d[2][4][4];
#pragma unroll
    for (int i = 0; i < 2; i++)
#pragma unroll
        for (int j = 0; j < 4; j++)
#pragma unroll
            for (int e = 0; e < 4; e++) d[i][j][e] = 0.0f;

    auto copy_tiles = [&](int kc, int s) {
        uint32_t sb = smb + s*STGB;
        const size_t ka = (size_t)kc*32 + csg*8;
        uint32_t doff = (uint32_t)cr*SPB + csg*16;
        cp16(sb + doff,            pl.Ah + (size_t)(row0 + cr)*512 + ka);
        cp16(sb + A_TILE + doff,   pl.Al + (size_t)(row0 + cr)*512 + ka);
        cp16(sb + 2*A_TILE + doff,                       pl.Bh + (size_t)(col0 + cr)*512 + ka);
        cp16(sb + 2*A_TILE + (uint32_t)br1*SPB + csg*16, pl.Bh + (size_t)(col0 + br1)*512 + ka);
    };

    // ldmatrix lane-address components
    const uint32_t aRow = (uint32_t)(wm*32 + (lid & 15));
    const uint32_t aK   = (uint32_t)((lid >> 4) * 8);
    const uint32_t bN   = (uint32_t)(wn*32 + ((lid >> 4) & 1)*8 + (lid & 7));
    const uint32_t bK   = (uint32_t)(((lid >> 3) & 1) * 8);

    copy_tiles(0, 0); cp_commit();
    int buf = 0;
    for (int kc = 0; kc < NKC; kc++) {
        if (kc + 1 < NKC) { copy_tiles(kc + 1, buf ^ 1); cp_commit(); cp_wait<1>(); }
        else              { cp_wait<0>(); }
        __syncthreads();

        const uint32_t ah_b = smb + buf*STGB;
        const uint32_t al_b = ah_b + A_TILE;
        const uint32_t bh_b = ah_b + 2*A_TILE;

#pragma unroll
        for (int kkh = 0; kkh < 32; kkh += 16) {
            uint32_t bh[4][2];
#pragma unroll
            for (int blk = 0; blk < 2; blk++) {
                uint32_t off = (bN + blk*16)*SPB + (bK + kkh)*2;
                uint32_t t[4];
                ldsm_x4(t, bh_b + off);
                bh[2*blk][0] = t[0]; bh[2*blk][1] = t[1];
                bh[2*blk+1][0] = t[2]; bh[2*blk+1][1] = t[3];
            }
#pragma unroll
            for (int i = 0; i < 2; i++) {
                uint32_t off = (aRow + i*16)*SPB + (aK + kkh)*2;
                uint32_t ah[4], al[4];
                ldsm_x4(ah, ah_b + off);
                ldsm_x4(al, al_b + off);
#pragma unroll
                for (int j = 0; j < 4; j++) {
                    mma16816(d[i][j], ah, bh[j]);
                    mma16816(d[i][j], al, bh[j]);
                }
            }
        }
        __syncthreads();
        buf ^= 1;
    }

#pragma unroll
    for (int i = 0; i < 2; i++) {
        long long r = row0 + wm*32 + i*16 + gid;
#pragma unroll
        for (int j = 0; j < 4; j++) {
            long long cn = col0 + wn*32 + j*8 + tig*2;
            *(float2*)&pl.out[r*pl.ldc + cn]       = make_float2(d[i][j][0], d[i][j][1]);
            *(float2*)&pl.out[(r+8)*pl.ldc + cn]   = make_float2(d[i][j][2], d[i][j][3]);
        }
    }
}

// ---------------- scalar segmented SGEMM (prologue Grx / dd0 only) ----------------
__device__ __forceinline__ void fma2(unsigned long long &d, unsigned long long a, unsigned long long b){
    asm("fma.rn.f32x2 %0, %1, %2, %0;" : "+l"(d) : "l"(a), "l"(b));
}
struct SPlane { const float* A; long long lda; const float* Bw; long long ldb;
                float* out; long long ldc; int K; int xmax; int kind; };
struct SStage { SPlane p[3]; };

template<int BN, int TM, int TN>
__global__ void __launch_bounds__((BN/TN)*(64/TM))
gemm_s(SStage SA)
{
    constexpr int BM = 64, BK = 16;
    constexpr int TX = BN/TN, TY = BM/TM, NT = TX*TY;
    constexpr int AW = 2*BM + 8;
    __shared__ __align__(16) float a_s[BK][AW];
    __shared__ __align__(16) float b_s[BK][BN];

    const SPlane pl = SA.p[blockIdx.z];
    if (pl.kind < 0) return;
    if ((int)blockIdx.x >= pl.xmax) return;

    const int tid  = threadIdx.x;
    const int tx   = tid % TX;
    const int ty   = tid / TX;
    const int row0 = blockIdx.y * BM;
    const int col0 = blockIdx.x * BN;

    unsigned long long acc[TM][TN/2];
#pragma unroll
    for (int i = 0; i < TM; i++)
#pragma unroll
        for (int j = 0; j < TN/2; j++) acc[i][j] = 0ull;

    for (int k0 = 0; k0 < pl.K; k0 += BK) {
#pragma unroll
        for (int e = tid; e < BM*BK/4; e += NT) {
            int r  = e >> 2;
            int kq = (e & 3) << 2;
            float4 v = *(const float4*)(pl.A + (long long)(row0 + r)*pl.lda + k0 + kq);
            *(float2*)&a_s[kq+0][2*r] = make_float2(v.x, v.x);
            *(float2*)&a_s[kq+1][2*r] = make_float2(v.y, v.y);
            *(float2*)&a_s[kq+2][2*r] = make_float2(v.z, v.z);
            *(float2*)&a_s[kq+3][2*r] = make_float2(v.w, v.w);
        }
#pragma unroll
        for (int e = tid; e < BK*BN/4; e += NT) {
            int kk = e / (BN/4);
            int n4 = (e % (BN/4)) * 4;
            *(float4*)&b_s[kk][n4] =
                *(const float4*)(pl.Bw + (long long)(k0+kk)*pl.ldb + col0 + n4);
        }
        __syncthreads();
#pragma unroll
        for (int kk = 0; kk < BK; kk++) {
            unsigned long long aa[TM], bq[TN/2];
            const ulonglong2* ap = (const ulonglong2*)&a_s[kk][2*(ty*TM)];
            const ulonglong2* bp = (const ulonglong2*)&b_s[kk][tx*TN];
#pragma unroll
            for (int i = 0; i < TM/2; i++) { ulonglong2 u = ap[i]; aa[2*i] = u.x; aa[2*i+1] = u.y; }
#pragma unroll
            for (int j = 0; j < TN/4; j++) { ulonglong2 v = bp[j]; bq[2*j] = v.x; bq[2*j+1] = v.y; }
#pragma unroll
            for (int i = 0; i < TM; i++)
#pragma unroll
                for (int j = 0; j < TN/2; j++)
                    fma2(acc[i][j], aa[i], bq[j]);
        }
        __syncthreads();
    }
#pragma unroll
    for (int i = 0; i < TM; i++) {
        long long r = row0 + ty*TM + i;
        float* orow = pl.out + r*pl.ldc + col0 + tx*TN;
#pragma unroll
        for (int j = 0; j < TN/2; j++)
            *(unsigned long long*)&orow[2*j] = acc[i][j];
    }
}

// ---------------- combined stage update (+ fp16 hi/lo h write) ----------------
struct UpdA {
    int valid0, valid1, valid2, pvalid;
    int t0, t1, t2, tp;
    const float *gx0, *gx1, *gx2;
    const float *wxb0, *wxb1, *wxb2, *whb0, *whb1, *whb2;
    const float *part, *dd0, *dd;
    float *h, *c;
    const float *pb; const float *pp; float *out;
};

__global__ void stage_update(UpdA u)
{
    const int rg = blockIdx.x >> 10;
    const long long idx = ((long long)(blockIdx.x & 1023))*256 + threadIdx.x;
    const int b = (int)(idx >> 9);
    const int n = (int)(idx & 511);

    if (rg < 3) {
        int valid = rg==0 ? u.valid0 : (rg==1 ? u.valid1 : u.valid2);
        if (!valid) return;
        int t = rg==0 ? u.t0 : (rg==1 ? u.t1 : u.t2);
        const float* gx  = rg==0 ? u.gx0  : (rg==1 ? u.gx1  : u.gx2);
        const float* wxb = rg==0 ? u.wxb0 : (rg==1 ? u.wxb1 : u.wxb2);
        const float* whb = rg==0 ? u.whb0 : (rg==1 ? u.whb1 : u.whb2);
        int pbase = rg==0 ? 0 : (rg==1 ? 1 : 3);
        int np    = rg + 1;

        const float* gxr = gx + ((long long)b*TT + t)*G4;
        float g0 = gxr[n]        + wxb[n]        + whb[n];
        float g1 = gxr[DD+n]     + wxb[DD+n]     + whb[DD+n];
        float g2 = gxr[2*DD+n]   + wxb[2*DD+n]   + whb[2*DD+n];
        float g3 = gxr[3*DD+n]   + wxb[3*DD+n]   + whb[3*DD+n];
        const float* pp = u.part + (long long)pbase*BB*G4 + (long long)b*G4;
        for (int z = 0; z < np; z++, pp += (long long)BB*G4) {
            g0 += pp[n]; g1 += pp[DD+n]; g2 += pp[2*DD+n]; g3 += pp[3*DD+n];
        }
        float f  = sigm(g0);
        float i  = sigm(g1);
        float o  = sigm(g2);
        float cb = tanhf(g3);
        float ddv = (rg == 0) ? tanhf(u.dd0[((long long)b*TT + t)*DD + n])
                              : u.dd[(long long)(rg-1)*BD + idx];
        float* cp = u.c + (long long)rg*BD;
        float cv = f*cp[idx] + i*cb + ddv;
        cp[idx] = cv;
        float hv = o * tanhf(cv);
        long long hoff = (((long long)(t & 3)*LL) + rg)*BD + idx;
        u.h[hoff] = hv;
        __half hh = __float2half_rn(hv);
        g_hbh[hoff] = hh;
        g_hbl[hoff] = __float2half_rn(hv - __half2float(hh));
    } else {
        if (!u.pvalid) return;
        float v = u.pb[n] + u.pp[idx] + u.pp[(long long)BB*OO + idx] + u.pp[2ll*BB*OO + idx];
        u.out[((long long)b*TT + u.tp)*OO + n] = v;
    }
}

// ---------------- weight image prep: transpose + fp16 (hi only) ----------------
struct WImg { const float* src; int N; long long off; };
struct WTab { WImg im[12]; };

__global__ void wprep(WTab T)
{
    WImg im = T.im[blockIdx.z];
    int idx = blockIdx.x*256 + threadIdx.x;       // over N*64 8-elem units
    if (idx >= im.N*64) return;
    int n  = idx >> 6;
    int ku = idx & 63;
    __half hi[8];
#pragma unroll
    for (int j = 0; j < 8; j++)
        hi[j] = __float2half_rn(im.src[(size_t)(ku*8 + j)*im.N + n]);
    size_t d = (size_t)im.off + (size_t)n*512 + (size_t)ku*8;
    *(uint4*)&g_wih[d] = *(uint4*)hi;
}

// ---------------- X -> fp16 hi/lo ----------------
__global__ void xconv(const float* __restrict__ X)
{
    long long i4 = ((long long)blockIdx.x*256 + threadIdx.x);
    const float4 v = *(const float4*)(X + i4*4);
    __half hi[4], lo[4];
    float xs[4] = {v.x, v.y, v.z, v.w};
#pragma unroll
    for (int j = 0; j < 4; j++) {
        hi[j] = __float2half_rn(xs[j]);
        lo[j] = __float2half_rn(xs[j] - __half2float(hi[j]));
    }
    *(uint2*)&g_xbh[i4*4] = *(uint2*)hi;
    *(uint2*)&g_xbl[i4*4] = *(uint2*)lo;
}

// ---------------- layer-0 key scan ----------------
__global__ void scan_d0(const float* __restrict__ grx0, const float* __restrict__ keys,
                        float* __restrict__ d0all)
{
    int i = blockIdx.x*256 + threadIdx.x;
    int b = i >> 6, kk = i & 63;
    float d = keys[i];
    for (int t = 0; t < TT; t++) {
        float g = grx0[((long long)b*TT + t)*KK + kk];
        d *= 1.0f/(1.0f + expf(-g));
        d0all[((long long)b*TT + t)*KK + kk] = d;
    }
}

// ---------------- state init ----------------
__global__ void init_kernel(float* __restrict__ h, float* __restrict__ c,
                            float* __restrict__ d, const float* __restrict__ keys)
{
    const __half z16 = __float2half_rn(0.0f);
    for (long long idx = (long long)blockIdx.x*256 + threadIdx.x;
         idx < 4ll*LL*BD; idx += (long long)gridDim.x*256) {
        h[idx] = 0.0f;
        g_hbh[idx] = z16;
        g_hbl[idx] = z16;
        if (idx < (long long)LL*BD)    c[idx] = 0.0f;
        if (idx < (long long)LL*BB*KK) d[idx] = keys[idx % (BB*KK)];
    }
}

// ---------------- host orchestration ----------------
static const long long IMG_OFF[12] = {
    0, 1048576, 2097152, 3145728, 4194304, 5242880,            // gate planes 0..5
    6291456, 6553600, 6815744,                                 // proj 0..2
    7077888, 8126464, 9175040                                  // gx 0..2
};

extern "C" void kernel_launch(void* const* d_in, const int* in_sizes, int n_in,
                              void* d_out, int out_size)
{
    const float* X    = (const float*)d_in[0];
    const float* keys = (const float*)d_in[1];

    const float *wx_w[LL], *wx_b[LL], *wh_w[LL], *wh_b[LL], *wr_w[LL], *wl_w[LL];
    if (in_sizes[4] == 512*2048) {
        for (int l = 0; l < LL; l++) {      // dict order
            int base = 2 + 6*l;
            wx_w[l] = (const float*)d_in[base+0];
            wx_b[l] = (const float*)d_in[base+1];
            wh_w[l] = (const float*)d_in[base+2];
            wh_b[l] = (const float*)d_in[base+3];
            wr_w[l] = (const float*)d_in[base+4];
            wl_w[l] = (const float*)d_in[base+5];
        }
    } else {
        for (int l = 0; l < LL; l++) {      // signature order
            wx_w[l] = (const float*)d_in[2 + 2*l];
            wx_b[l] = (const float*)d_in[3 + 2*l];
            wh_w[l] = (const float*)d_in[8 + 2*l];
            wh_b[l] = (const float*)d_in[9 + 2*l];
            wr_w[l] = (const float*)d_in[14 + l];
            wl_w[l] = (const float*)d_in[17 + l];
        }
    }
    const float* wd     = (const float*)d_in[20];
    const float* proj_w = (const float*)d_in[21];
    const float* proj_b = (const float*)d_in[22];
    float* out = (float*)d_out;

    float *p_gx, *p_Grx, *p_d0all, *p_dd0, *p_h, *p_c, *p_d, *p_dd, *p_part, *p_ppart;
    __half *p_wih, *p_xbh, *p_xbl, *p_hbh, *p_hbl;
    cudaGetSymbolAddress((void**)&p_gx,    g_gx);
    cudaGetSymbolAddress((void**)&p_Grx,   g_Grx);
    cudaGetSymbolAddress((void**)&p_d0all, g_d0all);
    cudaGetSymbolAddress((void**)&p_dd0,   g_dd0);
    cudaGetSymbolAddress((void**)&p_h,     g_h);
    cudaGetSymbolAddress((void**)&p_c,     g_c);
    cudaGetSymbolAddress((void**)&p_d,     g_d);
    cudaGetSymbolAddress((void**)&p_dd,    g_dd);
    cudaGetSymbolAddress((void**)&p_part,  g_part);
    cudaGetSymbolAddress((void**)&p_ppart, g_ppart);
    cudaGetSymbolAddress((void**)&p_wih,   g_wih);
    cudaGetSymbolAddress((void**)&p_xbh,   g_xbh);
    cudaGetSymbolAddress((void**)&p_xbl,   g_xbl);
    cudaGetSymbolAddress((void**)&p_hbh,   g_hbh);
    cudaGetSymbolAddress((void**)&p_hbl,   g_hbl);

    const int MSM = 2*STGB;   // 40960 B dynamic smem
    cudaFuncSetAttribute(mma_stage, cudaFuncAttributeMaxDynamicSharedMemorySize, MSM);

    auto hbh = [&](int l, int t) {
        int slot = (t < 0) ? 3 : (t & 3);
        return p_hbh + (((long long)slot*LL) + l)*BD;
    };
    auto hbl = [&](int l, int t) {
        int slot = (t < 0) ? 3 : (t & 3);
        return p_hbl + (((long long)slot*LL) + l)*BD;
    };

    // ---- prologue ----
    init_kernel<<<12288, 256>>>(p_h, p_c, p_d, keys);

    {
        WTab T{};
        T.im[0] = { wh_w[0], G4, IMG_OFF[0] };
        T.im[1] = { wh_w[1], G4, IMG_OFF[1] };
        T.im[2] = { wx_w[1] + (long long)CC*G4, G4, IMG_OFF[2] };
        T.im[3] = { wh_w[2], G4, IMG_OFF[3] };
        T.im[4] = { wx_w[2] + (long long)CC*G4, G4, IMG_OFF[4] };
        T.im[5] = { wx_w[2] + (long long)(CC+DD)*G4, G4, IMG_OFF[5] };
        for (int l = 0; l < LL; l++)
            T.im[6+l] = { proj_w + (long long)l*DD*OO, OO, IMG_OFF[6+l] };
        for (int l = 0; l < LL; l++)
            T.im[9+l] = { wx_w[l], G4, IMG_OFF[9+l] };
        dim3 g(512, 1, 12);
        wprep<<<g, 256>>>(T);
    }
    xconv<<<(BT*CC/4)/256, 256>>>(X);

    // Gx (tensor mma, z=3)
    {
        TStage SA{};
        for (int i = 0; i < 11; i++) SA.p[i].kind = -1;
        for (int l = 0; l < LL; l++)
            SA.p[l] = { p_xbh, p_xbl, p_wih + IMG_OFF[9+l],
                        p_gx + (long long)l*BT*G4, G4, 16, 0 };
        dim3 g(16, BT/64, 3);
        mma_stage<<<g, 256, MSM>>>(SA);
    }

    // Grx (scalar, N=64, z=3)
    {
        SStage SA{};
        for (int l = 0; l < LL; l++)
            SA.p[l] = { X, CC, wr_w[l], KK, p_Grx + (long long)l*BT*KK, KK, 512, 1, 0 };
        dim3 g(1, BT/64, 3);
        gemm_s<64,4,8><<<g, 128>>>(SA);
    }
    scan_d0<<<BB*KK/256, 256>>>(p_Grx, keys, p_d0all);
    {
        SStage SA{};
        SA.p[0] = { p_d0all, KK, wd, DD, p_dd0, DD, KK, 4, 0 };
        SA.p[1].kind = -1; SA.p[2].kind = -1;
        dim3 g(4, BT/64, 1);
        gemm_s<128,8,8><<<g, 128>>>(SA);
    }

    // ---- skewed-pipeline serial phase ----
    for (int s = 0; s <= TT + 2; s++) {
        const int t0 = s, t1 = s - 1, t2 = s - 2, tp = s - 3;
        const bool v0 = (t0 >= 0 && t0 < TT);
        const bool v1 = (t1 >= 0 && t1 < TT);
        const bool v2 = (t2 >= 0 && t2 < TT);
        const bool vp = (tp >= 0 && tp < TT);

        TStage SA{};
        for (int i = 0; i < 11; i++) SA.p[i].kind = -1;

        auto setg = [&](int pi, int al, int at, int img, float* o, long long ldc, int xmax) {
            SA.p[pi] = { hbh(al, at), hbl(al, at),
                         p_wih + IMG_OFF[img],
                         o, ldc, xmax, 0 };
        };
        if (v0)
            setg(0, 0, t0-1, 0, p_part + 0ll*BB*G4, G4, 16);
        if (v1) {
            setg(1, 1, t1-1, 1, p_part + 1ll*BB*G4, G4, 16);
            setg(2, 0, t1,   2, p_part + 2ll*BB*G4, G4, 16);
        }
        if (v2) {
            setg(3, 2, t2-1, 3, p_part + 3ll*BB*G4, G4, 16);
            setg(4, 0, t2,   4, p_part + 4ll*BB*G4, G4, 16);
            setg(5, 1, t2,   5, p_part + 5ll*BB*G4, G4, 16);
        }
        if (vp)
            for (int l = 0; l < LL; l++)
                setg(6+l, l, tp, 6+l, p_ppart + (long long)l*BB*OO, OO, 4);

        if (v1) {
            SA.p[9].kind = 1;
            K1A& a = SA.k1[0];
            a.hn = p_h + (long long)(t1 & 3)*LL*BD;
            a.hp = p_h + (long long)((t1-1) & 3)*LL*BD;
            a.grx = p_Grx + 1ll*BT*KK;
            a.wr = wr_w[1]; a.wl0 = wl_w[0]; a.wl1 = wl_w[1]; a.wd = wd;
            a.dst = p_d + 1ll*BB*KK; a.dd = p_dd;
            a.l = 1; a.t = t1;
        }
        if (v2) {
            SA.p[10].kind = 2;
            K1A& a = SA.k1[1];
            a.hn = p_h + (long long)(t2 & 3)*LL*BD;
            a.hp = p_h + (long long)((t2-1) & 3)*LL*BD;
            a.grx = p_Grx + 2ll*BT*KK;
            a.wr = wr_w[2]; a.wl0 = wl_w[0]; a.wl1 = wl_w[1]; a.wd = wd;
            a.dst = p_d + 2ll*BB*KK; a.dd = p_dd + BD;
            a.l = 2; a.t = t2;
        }

        dim3 gg(16, BB/64, 11);
        mma_stage<<<gg, 256, MSM>>>(SA);

        UpdA u{};
        u.valid0 = v0; u.valid1 = v1; u.valid2 = v2; u.pvalid = vp;
        u.t0 = t0; u.t1 = t1; u.t2 = t2; u.tp = tp;
        u.gx0 = p_gx + 0ll*BT*G4; u.gx1 = p_gx + 1ll*BT*G4; u.gx2 = p_gx + 2ll*BT*G4;
        u.wxb0 = wx_b[0]; u.wxb1 = wx_b[1]; u.wxb2 = wx_b[2];
        u.whb0 = wh_b[0]; u.whb1 = wh_b[1]; u.whb2 = wh_b[2];
        u.part = p_part; u.dd0 = p_dd0; u.dd = p_dd;
        u.h = p_h; u.c = p_c;
        u.pb = proj_b; u.pp = p_ppart; u.out = out;
        stage_update<<<4096, 256>>>(u);
    }
}

// round 17
// speedup vs baseline: 1.1009x; 1.1009x over previous
#include <cuda_runtime.h>
#include <cuda_fp16.h>
#include <math.h>
#include <stdint.h>

#define BB  512
#define TT  55
#define CC  512
#define DD  512
#define KK  64
#define LL  3
#define OO  512
#define BT  (BB*TT)      // 28160
#define BD  (BB*DD)      // 262144
#define G4  2048

// ---------------- device scratch ----------------
__device__ float g_gx[(size_t)LL*BT*G4];
__device__ float g_Grx[(size_t)LL*BT*KK];
__device__ float g_d0all[(size_t)BT*KK];
__device__ float g_dd0[(size_t)BT*DD];
__device__ float g_h[4*LL*BD];                    // fp32 h ring (k1 reads)
__device__ __half g_hbh[4*LL*BD];                 // fp16 hi ring
__device__ __half g_hbl[4*LL*BD];                 // fp16 lo ring
__device__ float g_c[LL*BD];
__device__ float g_d[LL*BB*KK];
__device__ float g_dd[2*BD];
__device__ float g_part[6*(size_t)BB*G4];
__device__ float g_ppart[3*(size_t)BB*OO];
__device__ __half g_xbh[(size_t)BT*CC];           // X fp16 (single-term)
// pre-transposed fp16 weight images, [n][k=512] row-major (12 images, hi only)
#define WIMG_TOT 10223616
__device__ __half g_wih[WIMG_TOT];

__device__ __forceinline__ float sigm(float x) { return 1.0f/(1.0f+expf(-x)); }

// ---- mma.sync m16n8k16 fp16 inputs, fp32 accum (base-target PTX) ----
__device__ __forceinline__ void mma16816(float* d, const uint32_t* a, const uint32_t* b) {
    asm volatile("mma.sync.aligned.m16n8k16.row.col.f32.f16.f16.f32 "
        "{%0,%1,%2,%3}, {%4,%5,%6,%7}, {%8,%9}, {%0,%1,%2,%3};"
        : "+f"(d[0]), "+f"(d[1]), "+f"(d[2]), "+f"(d[3])
        : "r"(a[0]), "r"(a[1]), "r"(a[2]), "r"(a[3]), "r"(b[0]), "r"(b[1]));
}
__device__ __forceinline__ void ldsm_x4(uint32_t* r, uint32_t addr) {
    asm volatile("ldmatrix.sync.aligned.m8n8.x4.shared.b16 {%0,%1,%2,%3}, [%4];"
        : "=r"(r[0]), "=r"(r[1]), "=r"(r[2]), "=r"(r[3]) : "r"(addr));
}
__device__ __forceinline__ uint32_t smem_u32(const void* p) {
    uint32_t a;
    asm("{ .reg .u64 t; cvta.to.shared.u64 t, %1; cvt.u32.u64 %0, t; }" : "=r"(a) : "l"(p));
    return a;
}
__device__ __forceinline__ void cp16(uint32_t dst, const void* src) {
    asm volatile("cp.async.cg.shared.global [%0], [%1], 16;" :: "r"(dst), "l"(src));
}
__device__ __forceinline__ void cp_commit() {
    asm volatile("cp.async.commit_group;" ::: "memory");
}
template<int N> __device__ __forceinline__ void cp_wait() {
    asm volatile("cp.async.wait_group %0;" :: "n"(N) : "memory");
}

// ---------------- key-gate body (256 threads; 8 batches per block) ----------------
struct K1A {
    const float *hp, *hn, *grx, *wr, *wl0, *wl1, *wd;
    float *dst, *dd;
    int l, t;
};
__device__ void k1_body(const K1A& a, int bx)
{
    __shared__ float dn_s[8][KK];
    const int tid = threadIdx.x;        // 256
    const int r   = tid >> 5;           // 0..7
    const int q   = tid & 31;
    const int b   = bx*8 + r;

    const long long gro = ((long long)b*TT + a.t)*KK;
    float acc0 = a.grx[gro + q];
    float acc1 = a.grx[gro + q + 32];
    for (int j = 0; j < a.l; j++) {
        const float* hnj = a.hn + (size_t)j*BD + (size_t)b*DD;
        const float* hpj = a.hp + (size_t)j*BD + (size_t)b*DD;
        const float* wrp = a.wr + (size_t)(CC + j*DD)*KK;
        const float* wlp = (j == 0 ? a.wl0 : a.wl1);
        float u0 = 0.f, u1 = 0.f;
#pragma unroll 4
        for (int m = 0; m < DD; m++) {
            float hv = hnj[m], pv = hpj[m];
            acc0 = fmaf(hv, wrp[(size_t)m*KK + q],      acc0);
            acc1 = fmaf(hv, wrp[(size_t)m*KK + q + 32], acc1);
            u0   = fmaf(pv, wlp[(size_t)m*KK + q],      u0);
            u1   = fmaf(pv, wlp[(size_t)m*KK + q + 32], u1);
        }
        acc0 += u0 * (1.0f/3.0f);
        acc1 += u1 * (1.0f/3.0f);
    }
    float dn0 = sigm(acc0) * a.dst[b*KK + q];
    float dn1 = sigm(acc1) * a.dst[b*KK + q + 32];
    a.dst[b*KK + q]      = dn0;
    a.dst[b*KK + q + 32] = dn1;
    dn_s[r][q]      = dn0;
    dn_s[r][q + 32] = dn1;
    __syncthreads();

    for (int e = tid; e < 8*DD; e += 256) {
        int r2 = e >> 9;
        int n  = e & 511;
        int bb = bx*8 + r2;
        float s = 0.0f;
#pragma unroll
        for (int qq = 0; qq < KK; qq++)
            s = fmaf(dn_s[r2][qq], a.wd[(size_t)qq*DD + n], s);
        a.dd[(size_t)bb*DD + n] = tanhf(s);
    }
}

// ---------------- mma stage kernel: fp16, 128x128 tile, TERMS in {1,2} ----------------
// Tile M=128,N=128,K=512 (16 chunks of 32, double-buffered). A row-major fp16 (hi[,lo]);
// B from pre-transposed [n][512] fp16 images. 8 warps (2x4), warp tile 64x32.
struct TPlane {
    const __half *Ah, *Al;          // [M][512] (Al unused when TERMS==1)
    const __half *Bh;               // image base [Np][512]
    float* out; long long ldc;
    int xmax; int kind;             // 0 gemm, -1 idle, 1 -> k1[0], 2 -> k1[1]
};
struct TStage { TPlane p[11]; K1A k1[2]; };

#define SPB   80        // smem row pitch in BYTES (40 halves)
#define TILEB 10240     // one 128x32 tile (bytes) with pitch
#define NKC   16

template<int TERMS>
__global__ void __launch_bounds__(256)
mma_stage(TStage SA)
{
    constexpr uint32_t STGB = (TERMS + 1) * TILEB;   // tiles per buffer: A-hi [,A-lo], B
    extern __shared__ __align__(16) char sm[];

    const TPlane pl = SA.p[blockIdx.z];
    if (pl.kind < 0) return;
    if (pl.kind > 0) {
        k1_body(SA.k1[pl.kind - 1], blockIdx.y * gridDim.x + blockIdx.x);
        return;
    }
    if ((int)blockIdx.x >= pl.xmax) return;

    const int tid = threadIdx.x;
    const int wid = tid >> 5, lid = tid & 31;
    const int wm = wid >> 2, wn = wid & 3;         // warp grid 2x4
    const int gid = lid >> 2, tig = lid & 3;
    const int row0 = blockIdx.y * 128;
    const int col0 = blockIdx.x * 128;
    const uint32_t smb = smem_u32(sm);

    const int cr0 = tid >> 2, csg = tid & 3;       // cp.async row/segment mapping
    const int cr1 = (tid + 256) >> 2;

    float d[4][4][4];
#pragma unroll
    for (int i = 0; i < 4; i++)
#pragma unroll
        for (int j = 0; j < 4; j++)
#pragma unroll
            for (int e = 0; e < 4; e++) d[i][j][e] = 0.0f;

    auto copy_tiles = [&](int kc, int s) {
        uint32_t sb = smb + s*STGB;
        const size_t ka = (size_t)kc*32 + csg*8;
#pragma unroll
        for (int it = 0; it < 2; it++) {
            int r = it ? cr1 : cr0;
            uint32_t doff = (uint32_t)r*SPB + csg*16;
            cp16(sb + doff, pl.Ah + (size_t)(row0 + r)*512 + ka);
            if (TERMS == 2)
                cp16(sb + TILEB + doff, pl.Al + (size_t)(row0 + r)*512 + ka);
            cp16(sb + TERMS*TILEB + doff, pl.Bh + (size_t)(col0 + r)*512 + ka);
        }
    };

    // ldmatrix lane-address components
    const uint32_t aRow = (uint32_t)(wm*64 + (lid & 15));
    const uint32_t aK   = (uint32_t)((lid >> 4) * 8);
    const uint32_t bN   = (uint32_t)(wn*32 + ((lid >> 4) & 1)*8 + (lid & 7));
    const uint32_t bK   = (uint32_t)(((lid >> 3) & 1) * 8);

    copy_tiles(0, 0); cp_commit();
    int buf = 0;
    for (int kc = 0; kc < NKC; kc++) {
        if (kc + 1 < NKC) { copy_tiles(kc + 1, buf ^ 1); cp_commit(); cp_wait<1>(); }
        else              { cp_wait<0>(); }
        __syncthreads();

        const uint32_t ah_b = smb + buf*STGB;
        const uint32_t al_b = ah_b + TILEB;
        const uint32_t bh_b = ah_b + TERMS*TILEB;

#pragma unroll
        for (int kkh = 0; kkh < 32; kkh += 16) {
            uint32_t bh[4][2];
#pragma unroll
            for (int blk = 0; blk < 2; blk++) {
                uint32_t off = (bN + blk*16)*SPB + (bK + kkh)*2;
                uint32_t t[4];
                ldsm_x4(t, bh_b + off);
                bh[2*blk][0] = t[0]; bh[2*blk][1] = t[1];
                bh[2*blk+1][0] = t[2]; bh[2*blk+1][1] = t[3];
            }
#pragma unroll
            for (int i = 0; i < 4; i++) {
                uint32_t off = (aRow + i*16)*SPB + (aK + kkh)*2;
                uint32_t ah[4], al[4];
                ldsm_x4(ah, ah_b + off);
                if (TERMS == 2) ldsm_x4(al, al_b + off);
#pragma unroll
                for (int j = 0; j < 4; j++) {
                    mma16816(d[i][j], ah, bh[j]);
                    if (TERMS == 2) mma16816(d[i][j], al, bh[j]);
                }
            }
        }
        __syncthreads();
        buf ^= 1;
    }

#pragma unroll
    for (int i = 0; i < 4; i++) {
        long long r = row0 + wm*64 + i*16 + gid;
#pragma unroll
        for (int j = 0; j < 4; j++) {
            long long cn = col0 + wn*32 + j*8 + tig*2;
            *(float2*)&pl.out[r*pl.ldc + cn]       = make_float2(d[i][j][0], d[i][j][1]);
            *(float2*)&pl.out[(r+8)*pl.ldc + cn]   = make_float2(d[i][j][2], d[i][j][3]);
        }
    }
}

// ---------------- scalar segmented SGEMM (prologue Grx / dd0 only) ----------------
__device__ __forceinline__ void fma2(unsigned long long &d, unsigned long long a, unsigned long long b){
    asm("fma.rn.f32x2 %0, %1, %2, %0;" : "+l"(d) : "l"(a), "l"(b));
}
struct SPlane { const float* A; long long lda; const float* Bw; long long ldb;
                float* out; long long ldc; int K; int xmax; int kind; };
struct SStage { SPlane p[3]; };

template<int BN, int TM, int TN>
__global__ void __launch_bounds__((BN/TN)*(64/TM))
gemm_s(SStage SA)
{
    constexpr int BM = 64, BK = 16;
    constexpr int TX = BN/TN, TY = BM/TM, NT = TX*TY;
    constexpr int AW = 2*BM + 8;
    __shared__ __align__(16) float a_s[BK][AW];
    __shared__ __align__(16) float b_s[BK][BN];

    const SPlane pl = SA.p[blockIdx.z];
    if (pl.kind < 0) return;
    if ((int)blockIdx.x >= pl.xmax) return;

    const int tid  = threadIdx.x;
    const int tx   = tid % TX;
    const int ty   = tid / TX;
    const int row0 = blockIdx.y * BM;
    const int col0 = blockIdx.x * BN;

    unsigned long long acc[TM][TN/2];
#pragma unroll
    for (int i = 0; i < TM; i++)
#pragma unroll
        for (int j = 0; j < TN/2; j++) acc[i][j] = 0ull;

    for (int k0 = 0; k0 < pl.K; k0 += BK) {
#pragma unroll
        for (int e = tid; e < BM*BK/4; e += NT) {
            int r  = e >> 2;
            int kq = (e & 3) << 2;
            float4 v = *(const float4*)(pl.A + (long long)(row0 + r)*pl.lda + k0 + kq);
            *(float2*)&a_s[kq+0][2*r] = make_float2(v.x, v.x);
            *(float2*)&a_s[kq+1][2*r] = make_float2(v.y, v.y);
            *(float2*)&a_s[kq+2][2*r] = make_float2(v.z, v.z);
            *(float2*)&a_s[kq+3][2*r] = make_float2(v.w, v.w);
        }
#pragma unroll
        for (int e = tid; e < BK*BN/4; e += NT) {
            int kk = e / (BN/4);
            int n4 = (e % (BN/4)) * 4;
            *(float4*)&b_s[kk][n4] =
                *(const float4*)(pl.Bw + (long long)(k0+kk)*pl.ldb + col0 + n4);
        }
        __syncthreads();
#pragma unroll
        for (int kk = 0; kk < BK; kk++) {
            unsigned long long aa[TM], bq[TN/2];
            const ulonglong2* ap = (const ulonglong2*)&a_s[kk][2*(ty*TM)];
            const ulonglong2* bp = (const ulonglong2*)&b_s[kk][tx*TN];
#pragma unroll
            for (int i = 0; i < TM/2; i++) { ulonglong2 u = ap[i]; aa[2*i] = u.x; aa[2*i+1] = u.y; }
#pragma unroll
            for (int j = 0; j < TN/4; j++) { ulonglong2 v = bp[j]; bq[2*j] = v.x; bq[2*j+1] = v.y; }
#pragma unroll
            for (int i = 0; i < TM; i++)
#pragma unroll
                for (int j = 0; j < TN/2; j++)
                    fma2(acc[i][j], aa[i], bq[j]);
        }
        __syncthreads();
    }
#pragma unroll
    for (int i = 0; i < TM; i++) {
        long long r = row0 + ty*TM + i;
        float* orow = pl.out + r*pl.ldc + col0 + tx*TN;
#pragma unroll
        for (int j = 0; j < TN/2; j++)
            *(unsigned long long*)&orow[2*j] = acc[i][j];
    }
}

// ---------------- combined stage update (+ fp16 hi/lo h write) ----------------
struct UpdA {
    int valid0, valid1, valid2, pvalid;
    int t0, t1, t2, tp;
    const float *gx0, *gx1, *gx2;
    const float *wxb0, *wxb1, *wxb2, *whb0, *whb1, *whb2;
    const float *part, *dd0, *dd;
    float *h, *c;
    const float *pb; const float *pp; float *out;
};

__global__ void stage_update(UpdA u)
{
    const int rg = blockIdx.x >> 10;
    const long long idx = ((long long)(blockIdx.x & 1023))*256 + threadIdx.x;
    const int b = (int)(idx >> 9);
    const int n = (int)(idx & 511);

    if (rg < 3) {
        int valid = rg==0 ? u.valid0 : (rg==1 ? u.valid1 : u.valid2);
        if (!valid) return;
        int t = rg==0 ? u.t0 : (rg==1 ? u.t1 : u.t2);
        const float* gx  = rg==0 ? u.gx0  : (rg==1 ? u.gx1  : u.gx2);
        const float* wxb = rg==0 ? u.wxb0 : (rg==1 ? u.wxb1 : u.wxb2);
        const float* whb = rg==0 ? u.whb0 : (rg==1 ? u.whb1 : u.whb2);
        int pbase = rg==0 ? 0 : (rg==1 ? 1 : 3);
        int np    = rg + 1;

        const float* gxr = gx + ((long long)b*TT + t)*G4;
        float g0 = gxr[n]        + wxb[n]        + whb[n];
        float g1 = gxr[DD+n]     + wxb[DD+n]     + whb[DD+n];
        float g2 = gxr[2*DD+n]   + wxb[2*DD+n]   + whb[2*DD+n];
        float g3 = gxr[3*DD+n]   + wxb[3*DD+n]   + whb[3*DD+n];
        const float* pp = u.part + (long long)pbase*BB*G4 + (long long)b*G4;
        for (int z = 0; z < np; z++, pp += (long long)BB*G4) {
            g0 += pp[n]; g1 += pp[DD+n]; g2 += pp[2*DD+n]; g3 += pp[3*DD+n];
        }
        float f  = sigm(g0);
        float i  = sigm(g1);
        float o  = sigm(g2);
        float cb = tanhf(g3);
        float ddv = (rg == 0) ? tanhf(u.dd0[((long long)b*TT + t)*DD + n])
                              : u.dd[(long long)(rg-1)*BD + idx];
        float* cp = u.c + (long long)rg*BD;
        float cv = f*cp[idx] + i*cb + ddv;
        cp[idx] = cv;
        float hv = o * tanhf(cv);
        long long hoff = (((long long)(t & 3)*LL) + rg)*BD + idx;
        u.h[hoff] = hv;
        __half hh = __float2half_rn(hv);
        g_hbh[hoff] = hh;
        g_hbl[hoff] = __float2half_rn(hv - __half2float(hh));
    } else {
        if (!u.pvalid) return;
        float v = u.pb[n] + u.pp[idx] + u.pp[(long long)BB*OO + idx] + u.pp[2ll*BB*OO + idx];
        u.out[((long long)b*TT + u.tp)*OO + n] = v;
    }
}

// ---------------- weight image prep: transpose + fp16 (hi only) ----------------
struct WImg { const float* src; int N; long long off; };
struct WTab { WImg im[12]; };

__global__ void wprep(WTab T)
{
    WImg im = T.im[blockIdx.z];
    int idx = blockIdx.x*256 + threadIdx.x;       // over N*64 8-elem units
    if (idx >= im.N*64) return;
    int n  = idx >> 6;
    int ku = idx & 63;
    __half hi[8];
#pragma unroll
    for (int j = 0; j < 8; j++)
        hi[j] = __float2half_rn(im.src[(size_t)(ku*8 + j)*im.N + n]);
    size_t d = (size_t)im.off + (size_t)n*512 + (size_t)ku*8;
    *(uint4*)&g_wih[d] = *(uint4*)hi;
}

// ---------------- X -> fp16 (single term) ----------------
__global__ void xconv(const float* __restrict__ X)
{
    long long i4 = ((long long)blockIdx.x*256 + threadIdx.x);
    const float4 v = *(const float4*)(X + i4*4);
    __half hi[4];
    hi[0] = __float2half_rn(v.x); hi[1] = __float2half_rn(v.y);
    hi[2] = __float2half_rn(v.z); hi[3] = __float2half_rn(v.w);
    *(uint2*)&g_xbh[i4*4] = *(uint2*)hi;
}

// ---------------- layer-0 key scan ----------------
__global__ void scan_d0(const float* __restrict__ grx0, const float* __restrict__ keys,
                        float* __restrict__ d0all)
{
    int i = blockIdx.x*256 + threadIdx.x;
    int b = i >> 6, kk = i & 63;
    float d = keys[i];
    for (int t = 0; t < TT; t++) {
        float g = grx0[((long long)b*TT + t)*KK + kk];
        d *= 1.0f/(1.0f + expf(-g));
        d0all[((long long)b*TT + t)*KK + kk] = d;
    }
}

// ---------------- state init ----------------
__global__ void init_kernel(float* __restrict__ h, float* __restrict__ c,
                            float* __restrict__ d, const float* __restrict__ keys)
{
    const __half z16 = __float2half_rn(0.0f);
    for (long long idx = (long long)blockIdx.x*256 + threadIdx.x;
         idx < 4ll*LL*BD; idx += (long long)gridDim.x*256) {
        h[idx] = 0.0f;
        g_hbh[idx] = z16;
        g_hbl[idx] = z16;
        if (idx < (long long)LL*BD)    c[idx] = 0.0f;
        if (idx < (long long)LL*BB*KK) d[idx] = keys[idx % (BB*KK)];
    }
}

// ---------------- host orchestration ----------------
static const long long IMG_OFF[12] = {
    0, 1048576, 2097152, 3145728, 4194304, 5242880,            // gate planes 0..5
    6291456, 6553600, 6815744,                                 // proj 0..2
    7077888, 8126464, 9175040                                  // gx 0..2
};

extern "C" void kernel_launch(void* const* d_in, const int* in_sizes, int n_in,
                              void* d_out, int out_size)
{
    const float* X    = (const float*)d_in[0];
    const float* keys = (const float*)d_in[1];

    const float *wx_w[LL], *wx_b[LL], *wh_w[LL], *wh_b[LL], *wr_w[LL], *wl_w[LL];
    if (in_sizes[4] == 512*2048) {
        for (int l = 0; l < LL; l++) {      // dict order
            int base = 2 + 6*l;
            wx_w[l] = (const float*)d_in[base+0];
            wx_b[l] = (const float*)d_in[base+1];
            wh_w[l] = (const float*)d_in[base+2];
            wh_b[l] = (const float*)d_in[base+3];
            wr_w[l] = (const float*)d_in[base+4];
            wl_w[l] = (const float*)d_in[base+5];
        }
    } else {
        for (int l = 0; l < LL; l++) {      // signature order
            wx_w[l] = (const float*)d_in[2 + 2*l];
            wx_b[l] = (const float*)d_in[3 + 2*l];
            wh_w[l] = (const float*)d_in[8 + 2*l];
            wh_b[l] = (const float*)d_in[9 + 2*l];
            wr_w[l] = (const float*)d_in[14 + l];
            wl_w[l] = (const float*)d_in[17 + l];
        }
    }
    const float* wd     = (const float*)d_in[20];
    const float* proj_w = (const float*)d_in[21];
    const float* proj_b = (const float*)d_in[22];
    float* out = (float*)d_out;

    float *p_gx, *p_Grx, *p_d0all, *p_dd0, *p_h, *p_c, *p_d, *p_dd, *p_part, *p_ppart;
    __half *p_wih, *p_xbh, *p_hbh, *p_hbl;
    cudaGetSymbolAddress((void**)&p_gx,    g_gx);
    cudaGetSymbolAddress((void**)&p_Grx,   g_Grx);
    cudaGetSymbolAddress((void**)&p_d0all, g_d0all);
    cudaGetSymbolAddress((void**)&p_dd0,   g_dd0);
    cudaGetSymbolAddress((void**)&p_h,     g_h);
    cudaGetSymbolAddress((void**)&p_c,     g_c);
    cudaGetSymbolAddress((void**)&p_d,     g_d);
    cudaGetSymbolAddress((void**)&p_dd,    g_dd);
    cudaGetSymbolAddress((void**)&p_part,  g_part);
    cudaGetSymbolAddress((void**)&p_ppart, g_ppart);
    cudaGetSymbolAddress((void**)&p_wih,   g_wih);
    cudaGetSymbolAddress((void**)&p_xbh,   g_xbh);
    cudaGetSymbolAddress((void**)&p_hbh,   g_hbh);
    cudaGetSymbolAddress((void**)&p_hbl,   g_hbl);

    const int MSM2 = 2*3*TILEB;   // 61440 B (2-term: Ah, Al, Bh)
    const int MSM1 = 2*2*TILEB;   // 40960 B (1-term: Ah, Bh)
    cudaFuncSetAttribute(mma_stage<2>, cudaFuncAttributeMaxDynamicSharedMemorySize, MSM2);
    cudaFuncSetAttribute(mma_stage<1>, cudaFuncAttributeMaxDynamicSharedMemorySize, MSM1);

    auto hbh = [&](int l, int t) {
        int slot = (t < 0) ? 3 : (t & 3);
        return p_hbh + (((long long)slot*LL) + l)*BD;
    };
    auto hbl = [&](int l, int t) {
        int slot = (t < 0) ? 3 : (t & 3);
        return p_hbl + (((long long)slot*LL) + l)*BD;
    };

    // ---- prologue ----
    init_kernel<<<12288, 256>>>(p_h, p_c, p_d, keys);

    {
        WTab T{};
        T.im[0] = { wh_w[0], G4, IMG_OFF[0] };
        T.im[1] = { wh_w[1], G4, IMG_OFF[1] };
        T.im[2] = { wx_w[1] + (long long)CC*G4, G4, IMG_OFF[2] };
        T.im[3] = { wh_w[2], G4, IMG_OFF[3] };
        T.im[4] = { wx_w[2] + (long long)CC*G4, G4, IMG_OFF[4] };
        T.im[5] = { wx_w[2] + (long long)(CC+DD)*G4, G4, IMG_OFF[5] };
        for (int l = 0; l < LL; l++)
            T.im[6+l] = { proj_w + (long long)l*DD*OO, OO, IMG_OFF[6+l] };
        for (int l = 0; l < LL; l++)
            T.im[9+l] = { wx_w[l], G4, IMG_OFF[9+l] };
        dim3 g(512, 1, 12);
        wprep<<<g, 256>>>(T);
    }
    xconv<<<(BT*CC/4)/256, 256>>>(X);

    // Gx (tensor mma, single-term, z=3)
    {
        TStage SA{};
        for (int i = 0; i < 11; i++) SA.p[i].kind = -1;
        for (int l = 0; l < LL; l++)
            SA.p[l] = { p_xbh, nullptr, p_wih + IMG_OFF[9+l],
                        p_gx + (long long)l*BT*G4, G4, 16, 0 };
        dim3 g(16, BT/128, 3);
        mma_stage<1><<<g, 256, MSM1>>>(SA);
    }

    // Grx (scalar, N=64, z=3)
    {
        SStage SA{};
        for (int l = 0; l < LL; l++)
            SA.p[l] = { X, CC, wr_w[l], KK, p_Grx + (long long)l*BT*KK, KK, 512, 1, 0 };
        dim3 g(1, BT/64, 3);
        gemm_s<64,4,8><<<g, 128>>>(SA);
    }
    scan_d0<<<BB*KK/256, 256>>>(p_Grx, keys, p_d0all);
    {
        SStage SA{};
        SA.p[0] = { p_d0all, KK, wd, DD, p_dd0, DD, KK, 4, 0 };
        SA.p[1].kind = -1; SA.p[2].kind = -1;
        dim3 g(4, BT/64, 1);
        gemm_s<128,8,8><<<g, 128>>>(SA);
    }

    // ---- skewed-pipeline serial phase ----
    for (int s = 0; s <= TT + 2; s++) {
        const int t0 = s, t1 = s - 1, t2 = s - 2, tp = s - 3;
        const bool v0 = (t0 >= 0 && t0 < TT);
        const bool v1 = (t1 >= 0 && t1 < TT);
        const bool v2 = (t2 >= 0 && t2 < TT);
        const bool vp = (tp >= 0 && tp < TT);

        TStage SA{};
        for (int i = 0; i < 11; i++) SA.p[i].kind = -1;

        auto setg = [&](int pi, int al, int at, int img, float* o, long long ldc, int xmax) {
            SA.p[pi] = { hbh(al, at), hbl(al, at),
                         p_wih + IMG_OFF[img],
                         o, ldc, xmax, 0 };
        };
        if (v0)
            setg(0, 0, t0-1, 0, p_part + 0ll*BB*G4, G4, 16);
        if (v1) {
            setg(1, 1, t1-1, 1, p_part + 1ll*BB*G4, G4, 16);
            setg(2, 0, t1,   2, p_part + 2ll*BB*G4, G4, 16);
        }
        if (v2) {
            setg(3, 2, t2-1, 3, p_part + 3ll*BB*G4, G4, 16);
            setg(4, 0, t2,   4, p_part + 4ll*BB*G4, G4, 16);
            setg(5, 1, t2,   5, p_part + 5ll*BB*G4, G4, 16);
        }
        if (vp)
            for (int l = 0; l < LL; l++)
                setg(6+l, l, tp, 6+l, p_ppart + (long long)l*BB*OO, OO, 4);

        if (v1) {
            SA.p[9].kind = 1;
            K1A& a = SA.k1[0];
            a.hn = p_h + (long long)(t1 & 3)*LL*BD;
            a.hp = p_h + (long long)((t1-1) & 3)*LL*BD;
            a.grx = p_Grx + 1ll*BT*KK;
            a.wr = wr_w[1]; a.wl0 = wl_w[0]; a.wl1 = wl_w[1]; a.wd = wd;
            a.dst = p_d + 1ll*BB*KK; a.dd = p_dd;
            a.l = 1; a.t = t1;
        }
        if (v2) {
            SA.p[10].kind = 2;
            K1A& a = SA.k1[1];
            a.hn = p_h + (long long)(t2 & 3)*LL*BD;
            a.hp = p_h + (long long)((t2-1) & 3)*LL*BD;
            a.grx = p_Grx + 2ll*BT*KK;
            a.wr = wr_w[2]; a.wl0 = wl_w[0]; a.wl1 = wl_w[1]; a.wd = wd;
            a.dst = p_d + 2ll*BB*KK; a.dd = p_dd + BD;
            a.l = 2; a.t = t2;
        }

        dim3 gg(16, 4, 11);
        mma_stage<2><<<gg, 256, MSM2>>>(SA);

        UpdA u{};
        u.valid0 = v0; u.valid1 = v1; u.valid2 = v2; u.pvalid = vp;
        u.t0 = t0; u.t1 = t1; u.t2 = t2; u.tp = tp;
        u.gx0 = p_gx + 0ll*BT*G4; u.gx1 = p_gx + 1ll*BT*G4; u.gx2 = p_gx + 2ll*BT*G4;
        u.wxb0 = wx_b[0]; u.wxb1 = wx_b[1]; u.wxb2 = wx_b[2];
        u.whb0 = wh_b[0]; u.whb1 = wh_b[1]; u.whb2 = wh_b[2];
        u.part = p_part; u.dd0 = p_dd0; u.dd = p_dd;
        u.h = p_h; u.c = p_c;
        u.pb = proj_b; u.pp = p_ppart; u.out = out;
        stage_update<<<4096, 256>>>(u);
    }
}